// round 2
// baseline (speedup 1.0000x reference)
#include <cuda_runtime.h>
#include <cuda_bf16.h>

#define NN 50000
#define NE 800000
#define DIM 96
#define H2 192
#define NG 64

// Scratch (static device globals; no allocation allowed)
__device__ float g_z [NN * DIM];   // (1+eps)*h + agg
__device__ float g_z1[NN * H2];    // hidden after GEMM1
__device__ float g_h0[NN * DIM];   // ping
__device__ float g_h1[NN * DIM];   // pong
__device__ float g_g [NG * DIM];   // pooled graph features

// ---------------------------------------------------------------------------
// z = (1 + eps[l]) * h      (vectorized float4)
// ---------------------------------------------------------------------------
__global__ void init_z_kernel(const float* __restrict__ h,
                              const float* __restrict__ eps, int l) {
    int i = blockIdx.x * blockDim.x + threadIdx.x;
    const int n4 = NN * DIM / 4;
    if (i < n4) {
        float s = 1.0f + eps[l];
        float4 v = ((const float4*)h)[i];
        v.x *= s; v.y *= s; v.z *= s; v.w *= s;
        ((float4*)g_z)[i] = v;
    }
}

// ---------------------------------------------------------------------------
// z[dst] += h[src]  over all edges. 32 edges per block; each edge row is
// 24 float4 chunks; vector atomicAdd (sm_90+) cuts atomic count 4x.
// ---------------------------------------------------------------------------
__global__ __launch_bounds__(256) void scatter_kernel(const float* __restrict__ h,
                                                      const int* __restrict__ ei) {
    __shared__ int s_src[32], s_dst[32];
    int tid = threadIdx.x;
    int e0 = blockIdx.x * 32;
    if (tid < 32) {
        s_src[tid] = ei[e0 + tid];
        s_dst[tid] = ei[NE + e0 + tid];
    }
    __syncthreads();
#pragma unroll
    for (int it = 0; it < 3; it++) {
        int idx = it * 256 + tid;        // 0..767 = 32 edges * 24 chunks
        int e = idx / 24;
        int c = idx % 24;
        float4 v = *(const float4*)&h[(size_t)s_src[e] * DIM + c * 4];
        atomicAdd((float4*)&g_z[(size_t)s_dst[e] * DIM] + c, v);
    }
}

// ---------------------------------------------------------------------------
// C[M,N] = relu(A[M,K] @ B[K,N] + bias[N])
// Register-blocked SGEMM: BM=64, BN=96, BK=32, thread tile 4x6, 256 threads.
// ---------------------------------------------------------------------------
__global__ __launch_bounds__(256) void gemm_relu_kernel(
    const float* __restrict__ A, const float* __restrict__ B,
    const float* __restrict__ bias, float* __restrict__ C,
    int M, int N, int K)
{
    const int BM = 64, BN = 96, BK = 32, TM = 4, TN = 6;
    __shared__ float As[BK][BM + 4];   // transposed A tile, padded
    __shared__ float Bs[BK][BN];

    int tid  = threadIdx.x;
    int brow = blockIdx.x * BM;
    int bcol = blockIdx.y * BN;
    int tRow = tid >> 4;       // 0..15
    int tCol = tid & 15;       // 0..15

    float acc[TM][TN];
#pragma unroll
    for (int i = 0; i < TM; i++)
#pragma unroll
        for (int j = 0; j < TN; j++) acc[i][j] = 0.0f;

    for (int k0 = 0; k0 < K; k0 += BK) {
        // ---- load A tile (64x32 = 512 float4, 2 per thread), transpose ----
#pragma unroll
        for (int i = 0; i < 2; i++) {
            int f4 = tid + 256 * i;
            int r  = f4 >> 3;            // 0..63
            int c  = (f4 & 7) << 2;      // 0,4,..,28
            int gr = brow + r;
            float4 v = make_float4(0.f, 0.f, 0.f, 0.f);
            if (gr < M) v = *(const float4*)&A[(size_t)gr * K + k0 + c];
            As[c + 0][r] = v.x; As[c + 1][r] = v.y;
            As[c + 2][r] = v.z; As[c + 3][r] = v.w;
        }
        // ---- load B tile (32x96 = 768 float4, 3 per thread) ----
#pragma unroll
        for (int i = 0; i < 3; i++) {
            int f4 = tid + 256 * i;
            int r  = f4 / 24;            // 0..31
            int c  = (f4 % 24) << 2;     // 0..92
            *(float4*)&Bs[r][c] = *(const float4*)&B[(size_t)(k0 + r) * N + bcol + c];
        }
        __syncthreads();

#pragma unroll
        for (int kk = 0; kk < BK; kk++) {
            float4 av = *(const float4*)&As[kk][tRow * TM];
            float a0 = av.x, a1 = av.y, a2 = av.z, a3 = av.w;
            float b[TN];
#pragma unroll
            for (int j = 0; j < TN; j++) b[j] = Bs[kk][tCol * TN + j];
#pragma unroll
            for (int j = 0; j < TN; j++) {
                acc[0][j] = fmaf(a0, b[j], acc[0][j]);
                acc[1][j] = fmaf(a1, b[j], acc[1][j]);
                acc[2][j] = fmaf(a2, b[j], acc[2][j]);
                acc[3][j] = fmaf(a3, b[j], acc[3][j]);
            }
        }
        __syncthreads();
    }

#pragma unroll
    for (int ii = 0; ii < TM; ii++) {
        int gr = brow + tRow * TM + ii;
        if (gr < M) {
#pragma unroll
            for (int jj = 0; jj < TN; jj++) {
                int gc = bcol + tCol * TN + jj;
                C[(size_t)gr * N + gc] = fmaxf(acc[ii][jj] + bias[gc], 0.0f);
            }
        }
    }
}

// ---------------------------------------------------------------------------
// Global add pool: g[batch[n]] += h[n]
// ---------------------------------------------------------------------------
__global__ void zero_g_kernel() {
    int i = blockIdx.x * blockDim.x + threadIdx.x;
    if (i < NG * DIM) g_g[i] = 0.0f;
}

__global__ void pool_kernel(const float* __restrict__ h,
                            const int* __restrict__ batch) {
    int i = blockIdx.x * blockDim.x + threadIdx.x;
    if (i < NN * 24) {
        int n = i / 24, c = i % 24;
        int b = batch[n];
        float4 v = *(const float4*)&h[(size_t)n * DIM + c * 4];
        atomicAdd((float4*)&g_g[(size_t)b * DIM] + c, v);
    }
}

// ---------------------------------------------------------------------------
// Final MLP: out = relu(g @ fW1 + fb1) @ fW2 + fb2   (one block)
// ---------------------------------------------------------------------------
__global__ __launch_bounds__(256) void final_kernel(
    const float* __restrict__ fW1, const float* __restrict__ fb1,
    const float* __restrict__ fW2, const float* __restrict__ fb2,
    float* __restrict__ out)
{
    __shared__ float gs[NG * DIM];   // 24 KB
    __shared__ float t1[NG * DIM];   // 24 KB
    int tid = threadIdx.x;
    for (int i = tid; i < NG * DIM; i += 256) gs[i] = g_g[i];
    __syncthreads();
    for (int o = tid; o < NG * DIM; o += 256) {
        int gi = o / DIM, j = o % DIM;
        float acc = fb1[j];
#pragma unroll 8
        for (int k = 0; k < DIM; k++)
            acc = fmaf(gs[gi * DIM + k], fW1[k * DIM + j], acc);
        t1[o] = fmaxf(acc, 0.0f);
    }
    __syncthreads();
    if (tid < NG) {
        float acc = fb2[0];
#pragma unroll 8
        for (int k = 0; k < DIM; k++)
            acc = fmaf(t1[tid * DIM + k], fW2[k], acc);
        out[tid] = acc;
    }
}

// ---------------------------------------------------------------------------
extern "C" void kernel_launch(void* const* d_in, const int* in_sizes, int n_in,
                              void* d_out, int out_size) {
    const float* x     = (const float*)d_in[0];
    const int*   ei    = (const int*)d_in[1];    // int32 (JAX x64 disabled)
    const int*   batch = (const int*)d_in[2];    // int32
    const float* W1    = (const float*)d_in[3];  // [3, 96, 192]
    const float* b1    = (const float*)d_in[4];  // [3, 192]
    const float* W2    = (const float*)d_in[5];  // [3, 192, 96]
    const float* b2    = (const float*)d_in[6];  // [3, 96]
    const float* eps   = (const float*)d_in[7];  // [3]
    const float* fW1   = (const float*)d_in[8];  // [96, 96]
    const float* fb1   = (const float*)d_in[9];  // [96]
    const float* fW2   = (const float*)d_in[10]; // [96, 1]
    const float* fb2   = (const float*)d_in[11]; // [1]
    float*       out   = (float*)d_out;

    float *zp, *z1p, *h0p, *h1p;
    cudaGetSymbolAddress((void**)&zp,  g_z);
    cudaGetSymbolAddress((void**)&z1p, g_z1);
    cudaGetSymbolAddress((void**)&h0p, g_h0);
    cudaGetSymbolAddress((void**)&h1p, g_h1);
    float* hbufs[2] = {h0p, h1p};

    const int mblocks = (NN + 63) / 64;   // 782

    const float* hin = x;
    for (int l = 0; l < 3; l++) {
        init_z_kernel<<<(NN * DIM / 4 + 255) / 256, 256>>>(hin, eps, l);
        scatter_kernel<<<NE / 32, 256>>>(hin, ei);
        gemm_relu_kernel<<<dim3(mblocks, 2), 256>>>(
            zp, W1 + (size_t)l * DIM * H2, b1 + (size_t)l * H2, z1p,
            NN, H2, DIM);
        float* hout = hbufs[l & 1];
        gemm_relu_kernel<<<dim3(mblocks, 1), 256>>>(
            z1p, W2 + (size_t)l * H2 * DIM, b2 + (size_t)l * DIM, hout,
            NN, DIM, H2);
        hin = hout;
    }

    zero_g_kernel<<<(NG * DIM + 255) / 256, 256>>>();
    pool_kernel<<<(NN * 24 + 255) / 256, 256>>>(hin, batch);
    final_kernel<<<1, 256>>>(fW1, fb1, fW2, fb2, out);
}

// round 4
// speedup vs baseline: 1.1737x; 1.1737x over previous
#include <cuda_runtime.h>
#include <cuda_bf16.h>
#include <cstdint>

#define NN 50000
#define NNP 50048          // padded to 391*128
#define NE 800000
#define DIM 96
#define H2 192
#define NG 64
#define P1 104             // GEMM1 smem K stride (elements)
#define P2 200             // GEMM2 smem K stride / z1 global row stride

// ---------------------------------------------------------------------------
// Scratch (static device globals)
// ---------------------------------------------------------------------------
__device__ float g_z [NNP * DIM];
__device__ __nv_bfloat16 g_z1h[NNP * P2];
__device__ __nv_bfloat16 g_z1l[NNP * P2];
__device__ float g_h0[NNP * DIM];
__device__ float g_h1[NNP * DIM];
__device__ float g_g [NG * DIM];
// Weight images, transposed to [N][Kpad], bf16 hi/lo
__device__ __nv_bfloat16 g_w1h[3 * 192 * P1];
__device__ __nv_bfloat16 g_w1l[3 * 192 * P1];
__device__ __nv_bfloat16 g_w2h[3 * 96 * P2];
__device__ __nv_bfloat16 g_w2l[3 * 96 * P2];

// ---------------------------------------------------------------------------
__device__ __forceinline__ uint32_t pack2(__nv_bfloat16 a, __nv_bfloat16 b) {
    return (uint32_t)__bfloat16_as_ushort(a) | ((uint32_t)__bfloat16_as_ushort(b) << 16);
}
__device__ __forceinline__ void split_bf16(float v, __nv_bfloat16& h, __nv_bfloat16& l) {
    h = __float2bfloat16(v);
    l = __float2bfloat16(v - __bfloat162float(h));
}
__device__ __forceinline__ void mma16816(float* d, const uint32_t* a, const uint32_t* b) {
    asm volatile("mma.sync.aligned.m16n8k16.row.col.f32.bf16.bf16.f32 "
        "{%0,%1,%2,%3}, {%4,%5,%6,%7}, {%8,%9}, {%0,%1,%2,%3};"
        : "+f"(d[0]), "+f"(d[1]), "+f"(d[2]), "+f"(d[3])
        : "r"(a[0]), "r"(a[1]), "r"(a[2]), "r"(a[3]), "r"(b[0]), "r"(b[1]));
}

// ---------------------------------------------------------------------------
// Weight prep: W[K,N] fp32 -> images [N][Kpad] bf16 hi/lo
// ---------------------------------------------------------------------------
__global__ void prep_w1(const float* __restrict__ W1) {
    int i = blockIdx.x * blockDim.x + threadIdx.x;
    if (i >= 3 * 192 * 96) return;
    int l = i / 18432, r = i % 18432;
    int n = r / 96, k = r % 96;
    float v = W1[(size_t)l * 96 * 192 + k * 192 + n];
    __nv_bfloat16 h, lo; split_bf16(v, h, lo);
    g_w1h[l * 192 * P1 + n * P1 + k] = h;
    g_w1l[l * 192 * P1 + n * P1 + k] = lo;
}
__global__ void prep_w2(const float* __restrict__ W2) {
    int i = blockIdx.x * blockDim.x + threadIdx.x;
    if (i >= 3 * 96 * 192) return;
    int l = i / 18432, r = i % 18432;
    int n = r / 192, k = r % 192;
    float v = W2[(size_t)l * 192 * 96 + k * 96 + n];
    __nv_bfloat16 h, lo; split_bf16(v, h, lo);
    g_w2h[l * 96 * P2 + n * P2 + k] = h;
    g_w2l[l * 96 * P2 + n * P2 + k] = lo;
}

// ---------------------------------------------------------------------------
// z = (1+eps[l]) * h
// ---------------------------------------------------------------------------
__global__ void init_z_kernel(const float* __restrict__ h,
                              const float* __restrict__ eps, int l) {
    int i = blockIdx.x * blockDim.x + threadIdx.x;
    const int n4 = NN * DIM / 4;
    if (i < n4) {
        float s = 1.0f + eps[l];
        float4 v = ((const float4*)h)[i];
        v.x *= s; v.y *= s; v.z *= s; v.w *= s;
        ((float4*)g_z)[i] = v;
    }
}

// ---------------------------------------------------------------------------
// z[dst] += h[src] over edges (float4 vector atomics)
// ---------------------------------------------------------------------------
__global__ __launch_bounds__(256) void scatter_kernel(const float* __restrict__ h,
                                                      const int* __restrict__ ei) {
    __shared__ int s_src[32], s_dst[32];
    int tid = threadIdx.x;
    int e0 = blockIdx.x * 32;
    if (tid < 32) {
        s_src[tid] = ei[e0 + tid];
        s_dst[tid] = ei[NE + e0 + tid];
    }
    __syncthreads();
#pragma unroll
    for (int it = 0; it < 3; it++) {
        int idx = it * 256 + tid;
        int e = idx / 24, c = idx % 24;
        float4 v = *(const float4*)&h[(size_t)s_src[e] * DIM + c * 4];
        atomicAdd((float4*)&g_z[(size_t)s_dst[e] * DIM] + c, v);
    }
}

// ---------------------------------------------------------------------------
// GEMM1 (mma.sync bf16 hi/lo): z1 = relu(z @ W1 + b1), out bf16 hi/lo @P2
// CTA: 128x192, K=96. 8 warps in 4(M)x2(N), warp tile 32x96.
// ---------------------------------------------------------------------------
#define G1_SMEM 134144
__global__ __launch_bounds__(256) void gemm1_mma(
    const float* __restrict__ A,
    const __nv_bfloat16* __restrict__ Bh, const __nv_bfloat16* __restrict__ Bl,
    const float* __restrict__ bias,
    __nv_bfloat16* __restrict__ Ch, __nv_bfloat16* __restrict__ Cl)
{
    extern __shared__ char sm[];
    float* bias_s = (float*)sm;
    __nv_bfloat16* sAh = (__nv_bfloat16*)(sm + 1024);
    __nv_bfloat16* sAl = (__nv_bfloat16*)(sm + 1024 + 26624);
    __nv_bfloat16* sBh = (__nv_bfloat16*)(sm + 1024 + 53248);
    __nv_bfloat16* sBl = (__nv_bfloat16*)(sm + 1024 + 93184);
    int tid = threadIdx.x, lane = tid & 31, wid = tid >> 5;
    int row0 = blockIdx.x * 128;

    if (tid < 192) bias_s[tid] = bias[tid];
    for (int i = tid; i < 2496; i += 256) {            // B: 192*104 bf16 = 2496 uint4
        ((uint4*)sBh)[i] = ((const uint4*)Bh)[i];
        ((uint4*)sBl)[i] = ((const uint4*)Bl)[i];
    }
    const float4* gA = (const float4*)(A + (size_t)row0 * DIM);
    for (int i = tid; i < 3072; i += 256) {            // A: 128*96 fp32
        int r = i / 24, c = i % 24;
        float4 v = gA[i];
        __nv_bfloat16 h0,l0,h1,l1,h2,l2,h3,l3;
        split_bf16(v.x,h0,l0); split_bf16(v.y,h1,l1);
        split_bf16(v.z,h2,l2); split_bf16(v.w,h3,l3);
        uint32_t off = r * P1 + c * 4;
        *(uint2*)&sAh[off] = make_uint2(pack2(h0,h1), pack2(h2,h3));
        *(uint2*)&sAl[off] = make_uint2(pack2(l0,l1), pack2(l2,l3));
    }
    __syncthreads();

    int wm = wid >> 1, wn = wid & 1;
    float d[2][12][4];
#pragma unroll
    for (int m = 0; m < 2; m++)
#pragma unroll
        for (int j = 0; j < 12; j++)
#pragma unroll
            for (int t = 0; t < 4; t++) d[m][j][t] = 0.0f;

    int arow = wm * 32 + (lane >> 2);
    int kc = (lane & 3) * 2;
#pragma unroll
    for (int k0 = 0; k0 < 96; k0 += 16) {
        uint32_t ah[2][4], al[2][4];
#pragma unroll
        for (int m = 0; m < 2; m++) {
            uint32_t o = (uint32_t)(arow + m * 16) * P1 + k0 + kc;
            ah[m][0] = *(uint32_t*)&sAh[o];
            ah[m][1] = *(uint32_t*)&sAh[o + 8 * P1];
            ah[m][2] = *(uint32_t*)&sAh[o + 8];
            ah[m][3] = *(uint32_t*)&sAh[o + 8 * P1 + 8];
            al[m][0] = *(uint32_t*)&sAl[o];
            al[m][1] = *(uint32_t*)&sAl[o + 8 * P1];
            al[m][2] = *(uint32_t*)&sAl[o + 8];
            al[m][3] = *(uint32_t*)&sAl[o + 8 * P1 + 8];
        }
#pragma unroll
        for (int j = 0; j < 12; j++) {
            uint32_t ob = (uint32_t)(wn * 96 + j * 8 + (lane >> 2)) * P1 + k0 + kc;
            uint32_t bh[2] = { *(uint32_t*)&sBh[ob], *(uint32_t*)&sBh[ob + 8] };
            uint32_t bl[2] = { *(uint32_t*)&sBl[ob], *(uint32_t*)&sBl[ob + 8] };
#pragma unroll
            for (int m = 0; m < 2; m++) {
                mma16816(d[m][j], ah[m], bh);
                mma16816(d[m][j], ah[m], bl);
                mma16816(d[m][j], al[m], bh);
            }
        }
    }
    __syncthreads();

    __nv_bfloat16* sCh = (__nv_bfloat16*)(sm + 1024);
    __nv_bfloat16* sCl = (__nv_bfloat16*)(sm + 1024 + 51200);
#pragma unroll
    for (int m = 0; m < 2; m++) {
        int r1 = wm * 32 + m * 16 + (lane >> 2);
#pragma unroll
        for (int j = 0; j < 12; j++) {
            int c0 = wn * 96 + j * 8 + (lane & 3) * 2;
            float v0 = fmaxf(d[m][j][0] + bias_s[c0],     0.0f);
            float v1 = fmaxf(d[m][j][1] + bias_s[c0 + 1], 0.0f);
            float v2 = fmaxf(d[m][j][2] + bias_s[c0],     0.0f);
            float v3 = fmaxf(d[m][j][3] + bias_s[c0 + 1], 0.0f);
            __nv_bfloat16 h0,l0,h1,l1,h2,l2,h3,l3;
            split_bf16(v0,h0,l0); split_bf16(v1,h1,l1);
            split_bf16(v2,h2,l2); split_bf16(v3,h3,l3);
            *(uint32_t*)&sCh[r1 * P2 + c0]       = pack2(h0, h1);
            *(uint32_t*)&sCl[r1 * P2 + c0]       = pack2(l0, l1);
            *(uint32_t*)&sCh[(r1 + 8) * P2 + c0] = pack2(h2, h3);
            *(uint32_t*)&sCl[(r1 + 8) * P2 + c0] = pack2(l2, l3);
        }
    }
    __syncthreads();
    uint4* gCh = (uint4*)(Ch + (size_t)row0 * P2);
    uint4* gCl = (uint4*)(Cl + (size_t)row0 * P2);
    for (int i = tid; i < 3200; i += 256) {            // 128*200 bf16 = 3200 uint4
        gCh[i] = ((uint4*)sCh)[i];
        gCl[i] = ((uint4*)sCl)[i];
    }
}

// ---------------------------------------------------------------------------
// GEMM2 (mma.sync bf16 hi/lo): h = relu(z1 @ W2 + b2), fp32 out
// CTA: 128x96, K=192. Warp grid 4(M)x2(N), warp tile 32x48.
// ---------------------------------------------------------------------------
#define G2_SMEM 180224
__global__ __launch_bounds__(256) void gemm2_mma(
    const __nv_bfloat16* __restrict__ Ah, const __nv_bfloat16* __restrict__ Al,
    const __nv_bfloat16* __restrict__ Bh, const __nv_bfloat16* __restrict__ Bl,
    const float* __restrict__ bias, float* __restrict__ C)
{
    extern __shared__ char sm[];
    float* bias_s = (float*)sm;
    __nv_bfloat16* sAh = (__nv_bfloat16*)(sm + 1024);
    __nv_bfloat16* sAl = (__nv_bfloat16*)(sm + 1024 + 51200);
    __nv_bfloat16* sBh = (__nv_bfloat16*)(sm + 1024 + 102400);
    __nv_bfloat16* sBl = (__nv_bfloat16*)(sm + 1024 + 140800);
    int tid = threadIdx.x, lane = tid & 31, wid = tid >> 5;
    int row0 = blockIdx.x * 128;

    if (tid < 96) bias_s[tid] = bias[tid];
    for (int i = tid; i < 2400; i += 256) {            // B: 96*200 bf16 = 2400 uint4
        ((uint4*)sBh)[i] = ((const uint4*)Bh)[i];
        ((uint4*)sBl)[i] = ((const uint4*)Bl)[i];
    }
    const uint4* gAh = (const uint4*)(Ah + (size_t)row0 * P2);
    const uint4* gAl = (const uint4*)(Al + (size_t)row0 * P2);
    for (int i = tid; i < 3200; i += 256) {            // A: 128*200 bf16 = 3200 uint4
        ((uint4*)sAh)[i] = gAh[i];
        ((uint4*)sAl)[i] = gAl[i];
    }
    __syncthreads();

    int wm = wid >> 1, wn = wid & 1;
    float d[2][6][4];
#pragma unroll
    for (int m = 0; m < 2; m++)
#pragma unroll
        for (int j = 0; j < 6; j++)
#pragma unroll
            for (int t = 0; t < 4; t++) d[m][j][t] = 0.0f;

    int arow = wm * 32 + (lane >> 2);
    int kc = (lane & 3) * 2;
#pragma unroll
    for (int k0 = 0; k0 < 192; k0 += 16) {
        uint32_t ah[2][4], al[2][4];
#pragma unroll
        for (int m = 0; m < 2; m++) {
            uint32_t o = (uint32_t)(arow + m * 16) * P2 + k0 + kc;
            ah[m][0] = *(uint32_t*)&sAh[o];
            ah[m][1] = *(uint32_t*)&sAh[o + 8 * P2];
            ah[m][2] = *(uint32_t*)&sAh[o + 8];
            ah[m][3] = *(uint32_t*)&sAh[o + 8 * P2 + 8];
            al[m][0] = *(uint32_t*)&sAl[o];
            al[m][1] = *(uint32_t*)&sAl[o + 8 * P2];
            al[m][2] = *(uint32_t*)&sAl[o + 8];
            al[m][3] = *(uint32_t*)&sAl[o + 8 * P2 + 8];
        }
#pragma unroll
        for (int j = 0; j < 6; j++) {
            uint32_t ob = (uint32_t)(wn * 48 + j * 8 + (lane >> 2)) * P2 + k0 + kc;
            uint32_t bh[2] = { *(uint32_t*)&sBh[ob], *(uint32_t*)&sBh[ob + 8] };
            uint32_t bl[2] = { *(uint32_t*)&sBl[ob], *(uint32_t*)&sBl[ob + 8] };
#pragma unroll
            for (int m = 0; m < 2; m++) {
                mma16816(d[m][j], ah[m], bh);
                mma16816(d[m][j], ah[m], bl);
                mma16816(d[m][j], al[m], bh);
            }
        }
    }
    __syncthreads();

    float* sC = (float*)(sm + 1024);                   // [128][100] fp32
#pragma unroll
    for (int m = 0; m < 2; m++) {
        int r1 = wm * 32 + m * 16 + (lane >> 2);
#pragma unroll
        for (int j = 0; j < 6; j++) {
            int c0 = wn * 48 + j * 8 + (lane & 3) * 2;
            *(float2*)&sC[r1 * 100 + c0] = make_float2(
                fmaxf(d[m][j][0] + bias_s[c0],     0.0f),
                fmaxf(d[m][j][1] + bias_s[c0 + 1], 0.0f));
            *(float2*)&sC[(r1 + 8) * 100 + c0] = make_float2(
                fmaxf(d[m][j][2] + bias_s[c0],     0.0f),
                fmaxf(d[m][j][3] + bias_s[c0 + 1], 0.0f));
        }
    }
    __syncthreads();
    float4* gC = (float4*)(C + (size_t)row0 * DIM);
    for (int i = tid; i < 3072; i += 256) {            // 128*96 fp32 = 3072 float4
        int r = i / 24, c = i % 24;
        gC[i] = *(float4*)&sC[r * 100 + c * 4];
    }
}

// ---------------------------------------------------------------------------
// Pool + final MLP
// ---------------------------------------------------------------------------
__global__ void zero_g_kernel() {
    int i = blockIdx.x * blockDim.x + threadIdx.x;
    if (i < NG * DIM) g_g[i] = 0.0f;
}
__global__ void pool_kernel(const float* __restrict__ h,
                            const int* __restrict__ batch) {
    int i = blockIdx.x * blockDim.x + threadIdx.x;
    if (i < NN * 24) {
        int n = i / 24, c = i % 24;
        int b = batch[n];
        float4 v = *(const float4*)&h[(size_t)n * DIM + c * 4];
        atomicAdd((float4*)&g_g[(size_t)b * DIM] + c, v);
    }
}
__global__ __launch_bounds__(256) void final_kernel(
    const float* __restrict__ fW1, const float* __restrict__ fb1,
    const float* __restrict__ fW2, const float* __restrict__ fb2,
    float* __restrict__ out)
{
    __shared__ float gs[NG * DIM];
    __shared__ float t1[NG * DIM];
    int tid = threadIdx.x;
    for (int i = tid; i < NG * DIM; i += 256) gs[i] = g_g[i];
    __syncthreads();
    for (int o = tid; o < NG * DIM; o += 256) {
        int gi = o / DIM, j = o % DIM;
        float acc = fb1[j];
#pragma unroll 8
        for (int k = 0; k < DIM; k++)
            acc = fmaf(gs[gi * DIM + k], fW1[k * DIM + j], acc);
        t1[o] = fmaxf(acc, 0.0f);
    }
    __syncthreads();
    if (tid < NG) {
        float acc = fb2[0];
#pragma unroll 8
        for (int k = 0; k < DIM; k++)
            acc = fmaf(t1[tid * DIM + k], fW2[k], acc);
        out[tid] = acc;
    }
}

// ---------------------------------------------------------------------------
extern "C" void kernel_launch(void* const* d_in, const int* in_sizes, int n_in,
                              void* d_out, int out_size) {
    const float* x     = (const float*)d_in[0];
    const int*   ei    = (const int*)d_in[1];
    const int*   batch = (const int*)d_in[2];
    const float* W1    = (const float*)d_in[3];
    const float* b1    = (const float*)d_in[4];
    const float* W2    = (const float*)d_in[5];
    const float* b2    = (const float*)d_in[6];
    const float* eps   = (const float*)d_in[7];
    const float* fW1   = (const float*)d_in[8];
    const float* fb1   = (const float*)d_in[9];
    const float* fW2   = (const float*)d_in[10];
    const float* fb2   = (const float*)d_in[11];
    float*       out   = (float*)d_out;

    static bool attr_done = false;
    if (!attr_done) {
        cudaFuncSetAttribute(gemm1_mma, cudaFuncAttributeMaxDynamicSharedMemorySize, G1_SMEM);
        cudaFuncSetAttribute(gemm2_mma, cudaFuncAttributeMaxDynamicSharedMemorySize, G2_SMEM);
        attr_done = true;
    }

    float *zp, *h0p, *h1p;
    __nv_bfloat16 *z1hp, *z1lp, *w1hp, *w1lp, *w2hp, *w2lp;
    cudaGetSymbolAddress((void**)&zp,   g_z);
    cudaGetSymbolAddress((void**)&h0p,  g_h0);
    cudaGetSymbolAddress((void**)&h1p,  g_h1);
    cudaGetSymbolAddress((void**)&z1hp, g_z1h);
    cudaGetSymbolAddress((void**)&z1lp, g_z1l);
    cudaGetSymbolAddress((void**)&w1hp, g_w1h);
    cudaGetSymbolAddress((void**)&w1lp, g_w1l);
    cudaGetSymbolAddress((void**)&w2hp, g_w2h);
    cudaGetSymbolAddress((void**)&w2lp, g_w2l);
    float* hbufs[2] = {h0p, h1p};

    prep_w1<<<216, 256>>>(W1);
    prep_w2<<<216, 256>>>(W2);

    const int tiles = NNP / 128;   // 391
    const float* hin = x;
    for (int l = 0; l < 3; l++) {
        init_z_kernel<<<(NN * DIM / 4 + 255) / 256, 256>>>(hin, eps, l);
        scatter_kernel<<<NE / 32, 256>>>(hin, ei);
        gemm1_mma<<<tiles, 256, G1_SMEM>>>(zp, w1hp + l * 192 * P1, w1lp + l * 192 * P1,
                                           b1 + (size_t)l * H2, z1hp, z1lp);
        float* hout = hbufs[l & 1];
        gemm2_mma<<<tiles, 256, G2_SMEM>>>(z1hp, z1lp, w2hp + l * 96 * P2, w2lp + l * 96 * P2,
                                           b2 + (size_t)l * DIM, hout);
        hin = hout;
    }

    zero_g_kernel<<<(NG * DIM + 255) / 256, 256>>>();
    pool_kernel<<<(NN * 24 + 255) / 256, 256>>>(hin, batch);
    final_kernel<<<1, 256>>>(fW1, fb1, fW2, fb2, out);
}

// round 6
// speedup vs baseline: 1.1985x; 1.0212x over previous
#include <cuda_runtime.h>
#include <cuda_bf16.h>
#include <cstdint>

#define NN 50000
#define NNP 50048          // padded to 391*128
#define NE 800000
#define DIM 96
#define H2 192
#define NG 64
#define P1 104             // GEMM1 smem K stride (elements)
#define P2 200             // GEMM2 smem K stride / z1 global row stride

// ---------------------------------------------------------------------------
// Scratch (static device globals)
// ---------------------------------------------------------------------------
__device__ float g_z [NNP * DIM];
__device__ __nv_bfloat16 g_z1h[NNP * P2];
__device__ __nv_bfloat16 g_z1l[NNP * P2];
__device__ float g_h0[NNP * DIM];
__device__ float g_h1[NNP * DIM];
__device__ float g_g [NG * DIM];
__device__ __nv_bfloat16 g_w1h[3 * 192 * P1];
__device__ __nv_bfloat16 g_w1l[3 * 192 * P1];
__device__ __nv_bfloat16 g_w2h[3 * 96 * P2];
__device__ __nv_bfloat16 g_w2l[3 * 96 * P2];
// CSR structures
__device__ int g_deg   [NN];
__device__ int g_start [NN + 1];
__device__ int g_cursor[NN];
__device__ int g_ssrc  [NE];

// ---------------------------------------------------------------------------
__device__ __forceinline__ uint32_t pack2(__nv_bfloat16 a, __nv_bfloat16 b) {
    return (uint32_t)__bfloat16_as_ushort(a) | ((uint32_t)__bfloat16_as_ushort(b) << 16);
}
__device__ __forceinline__ void split_bf16(float v, __nv_bfloat16& h, __nv_bfloat16& l) {
    h = __float2bfloat16(v);
    l = __float2bfloat16(v - __bfloat162float(h));
}
__device__ __forceinline__ void mma16816(float* d, const uint32_t* a, const uint32_t* b) {
    asm volatile("mma.sync.aligned.m16n8k16.row.col.f32.bf16.bf16.f32 "
        "{%0,%1,%2,%3}, {%4,%5,%6,%7}, {%8,%9}, {%0,%1,%2,%3};"
        : "+f"(d[0]), "+f"(d[1]), "+f"(d[2]), "+f"(d[3])
        : "r"(a[0]), "r"(a[1]), "r"(a[2]), "r"(a[3]), "r"(b[0]), "r"(b[1]));
}

// ---------------------------------------------------------------------------
// CSR build: zero -> histogram -> scan -> reorder
// (zero MUST be its own kernel: same-grid zero+atomicAdd is a race)
// ---------------------------------------------------------------------------
__global__ void zero_deg_kernel() {
    int i = blockIdx.x * blockDim.x + threadIdx.x;
    if (i < NN) g_deg[i] = 0;
}
__global__ void hist_kernel(const int* __restrict__ ei) {
    int i = blockIdx.x * blockDim.x + threadIdx.x;
    if (i < NE) atomicAdd(&g_deg[ei[NE + i]], 1);
}
// Single block, 1024 threads. Chunked sequential scan.
#define CHUNK 49
__global__ __launch_bounds__(1024) void scan_kernel() {
    __shared__ int csum[1024];
    int tid = threadIdx.x;
    int base = tid * CHUNK;
    int s = 0;
    for (int j = 0; j < CHUNK; j++) {
        int i = base + j;
        if (i < NN) s += g_deg[i];
    }
    csum[tid] = s;
    __syncthreads();
    for (int off = 1; off < 1024; off <<= 1) {
        int t = (tid >= off) ? csum[tid - off] : 0;
        __syncthreads();
        csum[tid] += t;
        __syncthreads();
    }
    int run = csum[tid] - s;     // exclusive prefix of this chunk
    for (int j = 0; j < CHUNK; j++) {
        int i = base + j;
        if (i < NN) {
            g_start[i]  = run;
            g_cursor[i] = run;
            run += g_deg[i];
        }
    }
    if (tid == 1023) g_start[NN] = csum[1023];
}
__global__ void reorder_kernel(const int* __restrict__ ei) {
    int e = blockIdx.x * blockDim.x + threadIdx.x;
    if (e < NE) {
        int dst = ei[NE + e];
        int pos = atomicAdd(&g_cursor[dst], 1);
        g_ssrc[pos] = ei[e];
    }
}

// ---------------------------------------------------------------------------
// Fused gather: z[n] = (1+eps[l])*h[n] + sum_{e in CSR[n]} h[src[e]]
// One warp per node; lane covers cols {lane, lane+32, lane+64}.
// ---------------------------------------------------------------------------
__global__ __launch_bounds__(256) void gather_kernel(const float* __restrict__ h,
                                                     const float* __restrict__ eps, int l) {
    int wid = threadIdx.x >> 5, lane = threadIdx.x & 31;
    int n = blockIdx.x * 8 + wid;
    if (n >= NN) return;
    int beg = g_start[n], end = g_start[n + 1];
    float a0 = 0.f, a1 = 0.f, a2 = 0.f;
    float b0 = 0.f, b1 = 0.f, b2 = 0.f;
    int e = beg;
    for (; e + 2 <= end; e += 2) {
        int s0 = g_ssrc[e], s1 = g_ssrc[e + 1];
        const float* p0 = h + (size_t)s0 * DIM + lane;
        const float* p1 = h + (size_t)s1 * DIM + lane;
        a0 += p0[0];  a1 += p0[32];  a2 += p0[64];
        b0 += p1[0];  b1 += p1[32];  b2 += p1[64];
    }
    if (e < end) {
        const float* p = h + (size_t)g_ssrc[e] * DIM + lane;
        a0 += p[0]; a1 += p[32]; a2 += p[64];
    }
    float sc = 1.0f + eps[l];
    const float* hp = h + (size_t)n * DIM + lane;
    float* zp = g_z + (size_t)n * DIM + lane;
    zp[0]  = fmaf(sc, hp[0],  a0 + b0);
    zp[32] = fmaf(sc, hp[32], a1 + b1);
    zp[64] = fmaf(sc, hp[64], a2 + b2);
}

// ---------------------------------------------------------------------------
// Weight prep
// ---------------------------------------------------------------------------
__global__ void prep_w1(const float* __restrict__ W1) {
    int i = blockIdx.x * blockDim.x + threadIdx.x;
    if (i >= 3 * 192 * 96) return;
    int l = i / 18432, r = i % 18432;
    int n = r / 96, k = r % 96;
    float v = W1[(size_t)l * 96 * 192 + k * 192 + n];
    __nv_bfloat16 h, lo; split_bf16(v, h, lo);
    g_w1h[l * 192 * P1 + n * P1 + k] = h;
    g_w1l[l * 192 * P1 + n * P1 + k] = lo;
}
__global__ void prep_w2(const float* __restrict__ W2) {
    int i = blockIdx.x * blockDim.x + threadIdx.x;
    if (i >= 3 * 96 * 192) return;
    int l = i / 18432, r = i % 18432;
    int n = r / 192, k = r % 192;
    float v = W2[(size_t)l * 192 * 96 + k * 96 + n];
    __nv_bfloat16 h, lo; split_bf16(v, h, lo);
    g_w2h[l * 96 * P2 + n * P2 + k] = h;
    g_w2l[l * 96 * P2 + n * P2 + k] = lo;
}

// ---------------------------------------------------------------------------
// GEMM1 (mma.sync bf16 hi/lo): z1 = relu(z @ W1 + b1), out bf16 hi/lo @P2
// ---------------------------------------------------------------------------
#define G1_SMEM 134144
__global__ __launch_bounds__(256) void gemm1_mma(
    const float* __restrict__ A,
    const __nv_bfloat16* __restrict__ Bh, const __nv_bfloat16* __restrict__ Bl,
    const float* __restrict__ bias,
    __nv_bfloat16* __restrict__ Ch, __nv_bfloat16* __restrict__ Cl)
{
    extern __shared__ char sm[];
    float* bias_s = (float*)sm;
    __nv_bfloat16* sAh = (__nv_bfloat16*)(sm + 1024);
    __nv_bfloat16* sAl = (__nv_bfloat16*)(sm + 1024 + 26624);
    __nv_bfloat16* sBh = (__nv_bfloat16*)(sm + 1024 + 53248);
    __nv_bfloat16* sBl = (__nv_bfloat16*)(sm + 1024 + 93184);
    int tid = threadIdx.x, lane = tid & 31, wid = tid >> 5;
    int row0 = blockIdx.x * 128;

    if (tid < 192) bias_s[tid] = bias[tid];
    for (int i = tid; i < 2496; i += 256) {
        ((uint4*)sBh)[i] = ((const uint4*)Bh)[i];
        ((uint4*)sBl)[i] = ((const uint4*)Bl)[i];
    }
    const float4* gA = (const float4*)(A + (size_t)row0 * DIM);
    for (int i = tid; i < 3072; i += 256) {
        int r = i / 24, c = i % 24;
        float4 v = gA[i];
        __nv_bfloat16 h0,l0,h1,l1,h2,l2,h3,l3;
        split_bf16(v.x,h0,l0); split_bf16(v.y,h1,l1);
        split_bf16(v.z,h2,l2); split_bf16(v.w,h3,l3);
        uint32_t off = r * P1 + c * 4;
        *(uint2*)&sAh[off] = make_uint2(pack2(h0,h1), pack2(h2,h3));
        *(uint2*)&sAl[off] = make_uint2(pack2(l0,l1), pack2(l2,l3));
    }
    __syncthreads();

    int wm = wid >> 1, wn = wid & 1;
    float d[2][12][4];
#pragma unroll
    for (int m = 0; m < 2; m++)
#pragma unroll
        for (int j = 0; j < 12; j++)
#pragma unroll
            for (int t = 0; t < 4; t++) d[m][j][t] = 0.0f;

    int arow = wm * 32 + (lane >> 2);
    int kc = (lane & 3) * 2;
#pragma unroll
    for (int k0 = 0; k0 < 96; k0 += 16) {
        uint32_t ah[2][4], al[2][4];
#pragma unroll
        for (int m = 0; m < 2; m++) {
            uint32_t o = (uint32_t)(arow + m * 16) * P1 + k0 + kc;
            ah[m][0] = *(uint32_t*)&sAh[o];
            ah[m][1] = *(uint32_t*)&sAh[o + 8 * P1];
            ah[m][2] = *(uint32_t*)&sAh[o + 8];
            ah[m][3] = *(uint32_t*)&sAh[o + 8 * P1 + 8];
            al[m][0] = *(uint32_t*)&sAl[o];
            al[m][1] = *(uint32_t*)&sAl[o + 8 * P1];
            al[m][2] = *(uint32_t*)&sAl[o + 8];
            al[m][3] = *(uint32_t*)&sAl[o + 8 * P1 + 8];
        }
#pragma unroll
        for (int j = 0; j < 12; j++) {
            uint32_t ob = (uint32_t)(wn * 96 + j * 8 + (lane >> 2)) * P1 + k0 + kc;
            uint32_t bh[2] = { *(uint32_t*)&sBh[ob], *(uint32_t*)&sBh[ob + 8] };
            uint32_t bl[2] = { *(uint32_t*)&sBl[ob], *(uint32_t*)&sBl[ob + 8] };
#pragma unroll
            for (int m = 0; m < 2; m++) {
                mma16816(d[m][j], ah[m], bh);
                mma16816(d[m][j], ah[m], bl);
                mma16816(d[m][j], al[m], bh);
            }
        }
    }
    __syncthreads();

    __nv_bfloat16* sCh = (__nv_bfloat16*)(sm + 1024);
    __nv_bfloat16* sCl = (__nv_bfloat16*)(sm + 1024 + 51200);
#pragma unroll
    for (int m = 0; m < 2; m++) {
        int r1 = wm * 32 + m * 16 + (lane >> 2);
#pragma unroll
        for (int j = 0; j < 12; j++) {
            int c0 = wn * 96 + j * 8 + (lane & 3) * 2;
            float v0 = fmaxf(d[m][j][0] + bias_s[c0],     0.0f);
            float v1 = fmaxf(d[m][j][1] + bias_s[c0 + 1], 0.0f);
            float v2 = fmaxf(d[m][j][2] + bias_s[c0],     0.0f);
            float v3 = fmaxf(d[m][j][3] + bias_s[c0 + 1], 0.0f);
            __nv_bfloat16 h0,l0,h1,l1,h2,l2,h3,l3;
            split_bf16(v0,h0,l0); split_bf16(v1,h1,l1);
            split_bf16(v2,h2,l2); split_bf16(v3,h3,l3);
            *(uint32_t*)&sCh[r1 * P2 + c0]       = pack2(h0, h1);
            *(uint32_t*)&sCl[r1 * P2 + c0]       = pack2(l0, l1);
            *(uint32_t*)&sCh[(r1 + 8) * P2 + c0] = pack2(h2, h3);
            *(uint32_t*)&sCl[(r1 + 8) * P2 + c0] = pack2(l2, l3);
        }
    }
    __syncthreads();
    uint4* gCh = (uint4*)(Ch + (size_t)row0 * P2);
    uint4* gCl = (uint4*)(Cl + (size_t)row0 * P2);
    for (int i = tid; i < 3200; i += 256) {
        gCh[i] = ((uint4*)sCh)[i];
        gCl[i] = ((uint4*)sCl)[i];
    }
}

// ---------------------------------------------------------------------------
// GEMM2 (mma.sync bf16 hi/lo): h = relu(z1 @ W2 + b2), fp32 out
// ---------------------------------------------------------------------------
#define G2_SMEM 180224
__global__ __launch_bounds__(256) void gemm2_mma(
    const __nv_bfloat16* __restrict__ Ah, const __nv_bfloat16* __restrict__ Al,
    const __nv_bfloat16* __restrict__ Bh, const __nv_bfloat16* __restrict__ Bl,
    const float* __restrict__ bias, float* __restrict__ C)
{
    extern __shared__ char sm[];
    float* bias_s = (float*)sm;
    __nv_bfloat16* sAh = (__nv_bfloat16*)(sm + 1024);
    __nv_bfloat16* sAl = (__nv_bfloat16*)(sm + 1024 + 51200);
    __nv_bfloat16* sBh = (__nv_bfloat16*)(sm + 1024 + 102400);
    __nv_bfloat16* sBl = (__nv_bfloat16*)(sm + 1024 + 140800);
    int tid = threadIdx.x, lane = tid & 31, wid = tid >> 5;
    int row0 = blockIdx.x * 128;

    if (tid < 96) bias_s[tid] = bias[tid];
    for (int i = tid; i < 2400; i += 256) {
        ((uint4*)sBh)[i] = ((const uint4*)Bh)[i];
        ((uint4*)sBl)[i] = ((const uint4*)Bl)[i];
    }
    const uint4* gAh = (const uint4*)(Ah + (size_t)row0 * P2);
    const uint4* gAl = (const uint4*)(Al + (size_t)row0 * P2);
    for (int i = tid; i < 3200; i += 256) {
        ((uint4*)sAh)[i] = gAh[i];
        ((uint4*)sAl)[i] = gAl[i];
    }
    __syncthreads();

    int wm = wid >> 1, wn = wid & 1;
    float d[2][6][4];
#pragma unroll
    for (int m = 0; m < 2; m++)
#pragma unroll
        for (int j = 0; j < 6; j++)
#pragma unroll
            for (int t = 0; t < 4; t++) d[m][j][t] = 0.0f;

    int arow = wm * 32 + (lane >> 2);
    int kc = (lane & 3) * 2;
#pragma unroll
    for (int k0 = 0; k0 < 192; k0 += 16) {
        uint32_t ah[2][4], al[2][4];
#pragma unroll
        for (int m = 0; m < 2; m++) {
            uint32_t o = (uint32_t)(arow + m * 16) * P2 + k0 + kc;
            ah[m][0] = *(uint32_t*)&sAh[o];
            ah[m][1] = *(uint32_t*)&sAh[o + 8 * P2];
            ah[m][2] = *(uint32_t*)&sAh[o + 8];
            ah[m][3] = *(uint32_t*)&sAh[o + 8 * P2 + 8];
            al[m][0] = *(uint32_t*)&sAl[o];
            al[m][1] = *(uint32_t*)&sAl[o + 8 * P2];
            al[m][2] = *(uint32_t*)&sAl[o + 8];
            al[m][3] = *(uint32_t*)&sAl[o + 8 * P2 + 8];
        }
#pragma unroll
        for (int j = 0; j < 6; j++) {
            uint32_t ob = (uint32_t)(wn * 48 + j * 8 + (lane >> 2)) * P2 + k0 + kc;
            uint32_t bh[2] = { *(uint32_t*)&sBh[ob], *(uint32_t*)&sBh[ob + 8] };
            uint32_t bl[2] = { *(uint32_t*)&sBl[ob], *(uint32_t*)&sBl[ob + 8] };
#pragma unroll
            for (int m = 0; m < 2; m++) {
                mma16816(d[m][j], ah[m], bh);
                mma16816(d[m][j], ah[m], bl);
                mma16816(d[m][j], al[m], bh);
            }
        }
    }
    __syncthreads();

    float* sC = (float*)(sm + 1024);
#pragma unroll
    for (int m = 0; m < 2; m++) {
        int r1 = wm * 32 + m * 16 + (lane >> 2);
#pragma unroll
        for (int j = 0; j < 6; j++) {
            int c0 = wn * 48 + j * 8 + (lane & 3) * 2;
            *(float2*)&sC[r1 * 100 + c0] = make_float2(
                fmaxf(d[m][j][0] + bias_s[c0],     0.0f),
                fmaxf(d[m][j][1] + bias_s[c0 + 1], 0.0f));
            *(float2*)&sC[(r1 + 8) * 100 + c0] = make_float2(
                fmaxf(d[m][j][2] + bias_s[c0],     0.0f),
                fmaxf(d[m][j][3] + bias_s[c0 + 1], 0.0f));
        }
    }
    __syncthreads();
    float4* gC = (float4*)(C + (size_t)row0 * DIM);
    for (int i = tid; i < 3072; i += 256) {
        int r = i / 24, c = i % 24;
        gC[i] = *(float4*)&sC[r * 100 + c * 4];
    }
}

// ---------------------------------------------------------------------------
// Pool + final MLP
// ---------------------------------------------------------------------------
__global__ void zero_g_kernel() {
    int i = blockIdx.x * blockDim.x + threadIdx.x;
    if (i < NG * DIM) g_g[i] = 0.0f;
}
__global__ void pool_kernel(const float* __restrict__ h,
                            const int* __restrict__ batch) {
    int i = blockIdx.x * blockDim.x + threadIdx.x;
    if (i < NN * 24) {
        int n = i / 24, c = i % 24;
        int b = batch[n];
        float4 v = *(const float4*)&h[(size_t)n * DIM + c * 4];
        atomicAdd((float4*)&g_g[(size_t)b * DIM] + c, v);
    }
}
__global__ __launch_bounds__(256) void final_kernel(
    const float* __restrict__ fW1, const float* __restrict__ fb1,
    const float* __restrict__ fW2, const float* __restrict__ fb2,
    float* __restrict__ out)
{
    __shared__ float gs[NG * DIM];
    __shared__ float t1[NG * DIM];
    int tid = threadIdx.x;
    for (int i = tid; i < NG * DIM; i += 256) gs[i] = g_g[i];
    __syncthreads();
    for (int o = tid; o < NG * DIM; o += 256) {
        int gi = o / DIM, j = o % DIM;
        float acc = fb1[j];
#pragma unroll 8
        for (int k = 0; k < DIM; k++)
            acc = fmaf(gs[gi * DIM + k], fW1[k * DIM + j], acc);
        t1[o] = fmaxf(acc, 0.0f);
    }
    __syncthreads();
    if (tid < NG) {
        float acc = fb2[0];
#pragma unroll 8
        for (int k = 0; k < DIM; k++)
            acc = fmaf(t1[tid * DIM + k], fW2[k], acc);
        out[tid] = acc;
    }
}

// ---------------------------------------------------------------------------
extern "C" void kernel_launch(void* const* d_in, const int* in_sizes, int n_in,
                              void* d_out, int out_size) {
    const float* x     = (const float*)d_in[0];
    const int*   ei    = (const int*)d_in[1];
    const int*   batch = (const int*)d_in[2];
    const float* W1    = (const float*)d_in[3];
    const float* b1    = (const float*)d_in[4];
    const float* W2    = (const float*)d_in[5];
    const float* b2    = (const float*)d_in[6];
    const float* eps   = (const float*)d_in[7];
    const float* fW1   = (const float*)d_in[8];
    const float* fb1   = (const float*)d_in[9];
    const float* fW2   = (const float*)d_in[10];
    const float* fb2   = (const float*)d_in[11];
    float*       out   = (float*)d_out;

    static bool attr_done = false;
    if (!attr_done) {
        cudaFuncSetAttribute(gemm1_mma, cudaFuncAttributeMaxDynamicSharedMemorySize, G1_SMEM);
        cudaFuncSetAttribute(gemm2_mma, cudaFuncAttributeMaxDynamicSharedMemorySize, G2_SMEM);
        attr_done = true;
    }

    float *zp, *h0p, *h1p;
    __nv_bfloat16 *z1hp, *z1lp, *w1hp, *w1lp, *w2hp, *w2lp;
    cudaGetSymbolAddress((void**)&zp,   g_z);
    cudaGetSymbolAddress((void**)&h0p,  g_h0);
    cudaGetSymbolAddress((void**)&h1p,  g_h1);
    cudaGetSymbolAddress((void**)&z1hp, g_z1h);
    cudaGetSymbolAddress((void**)&z1lp, g_z1l);
    cudaGetSymbolAddress((void**)&w1hp, g_w1h);
    cudaGetSymbolAddress((void**)&w1lp, g_w1l);
    cudaGetSymbolAddress((void**)&w2hp, g_w2h);
    cudaGetSymbolAddress((void**)&w2lp, g_w2l);
    float* hbufs[2] = {h0p, h1p};

    // CSR build (edge_index constant -> reused across layers)
    zero_deg_kernel<<<(NN + 255) / 256, 256>>>();
    hist_kernel<<<(NE + 255) / 256, 256>>>(ei);
    scan_kernel<<<1, 1024>>>();
    reorder_kernel<<<(NE + 255) / 256, 256>>>(ei);

    prep_w1<<<216, 256>>>(W1);
    prep_w2<<<216, 256>>>(W2);

    const int tiles = NNP / 128;   // 391
    const float* hin = x;
    for (int l = 0; l < 3; l++) {
        gather_kernel<<<(NN + 7) / 8, 256>>>(hin, eps, l);
        gemm1_mma<<<tiles, 256, G1_SMEM>>>(zp, w1hp + l * 192 * P1, w1lp + l * 192 * P1,
                                           b1 + (size_t)l * H2, z1hp, z1lp);
        float* hout = hbufs[l & 1];
        gemm2_mma<<<tiles, 256, G2_SMEM>>>(z1hp, z1lp, w2hp + l * 96 * P2, w2lp + l * 96 * P2,
                                           b2 + (size_t)l * DIM, hout);
        hin = hout;
    }

    zero_g_kernel<<<(NG * DIM + 255) / 256, 256>>>();
    pool_kernel<<<(NN * 24 + 255) / 256, 256>>>(hin, batch);
    final_kernel<<<1, 256>>>(fW1, fb1, fW2, fb2, out);
}

// round 7
// speedup vs baseline: 1.3502x; 1.1265x over previous
#include <cuda_runtime.h>
#include <cuda_bf16.h>
#include <cstdint>

#define NN 50000
#define NNP 50048          // padded to 391*128
#define NE 800000
#define DIM 96
#define H2 192
#define NG 64
#define P1 104             // GEMM1 smem K stride (elements)
#define P2 200             // GEMM2 smem K stride (elements)

// ---------------------------------------------------------------------------
// Scratch (static device globals)
// ---------------------------------------------------------------------------
__device__ float g_z [NNP * DIM];
__device__ float g_h0[NNP * DIM];
__device__ float g_h1[NNP * DIM];
__device__ float g_g [NG * DIM];
__device__ __nv_bfloat16 g_w1h[3 * 192 * P1];
__device__ __nv_bfloat16 g_w1l[3 * 192 * P1];
__device__ __nv_bfloat16 g_w2h[3 * 96 * P2];
__device__ __nv_bfloat16 g_w2l[3 * 96 * P2];
// CSR structures
__device__ int g_deg   [NN];
__device__ int g_start [NN + 1];
__device__ int g_cursor[NN];
__device__ int g_ssrc  [NE];

// ---------------------------------------------------------------------------
__device__ __forceinline__ uint32_t pack2(__nv_bfloat16 a, __nv_bfloat16 b) {
    return (uint32_t)__bfloat16_as_ushort(a) | ((uint32_t)__bfloat16_as_ushort(b) << 16);
}
__device__ __forceinline__ void split_bf16(float v, __nv_bfloat16& h, __nv_bfloat16& l) {
    h = __float2bfloat16(v);
    l = __float2bfloat16(v - __bfloat162float(h));
}
__device__ __forceinline__ void mma16816(float* d, const uint32_t* a, const uint32_t* b) {
    asm volatile("mma.sync.aligned.m16n8k16.row.col.f32.bf16.bf16.f32 "
        "{%0,%1,%2,%3}, {%4,%5,%6,%7}, {%8,%9}, {%0,%1,%2,%3};"
        : "+f"(d[0]), "+f"(d[1]), "+f"(d[2]), "+f"(d[3])
        : "r"(a[0]), "r"(a[1]), "r"(a[2]), "r"(a[3]), "r"(b[0]), "r"(b[1]));
}

// ---------------------------------------------------------------------------
// CSR build: zero -> histogram -> scan -> reorder
// ---------------------------------------------------------------------------
__global__ void zero_deg_kernel() {
    int i = blockIdx.x * blockDim.x + threadIdx.x;
    if (i < NN) g_deg[i] = 0;
}
__global__ void hist_kernel(const int* __restrict__ ei) {
    int i = blockIdx.x * blockDim.x + threadIdx.x;
    if (i < NE) atomicAdd(&g_deg[ei[NE + i]], 1);
}
#define CHUNK 49
__global__ __launch_bounds__(1024) void scan_kernel() {
    __shared__ int csum[1024];
    int tid = threadIdx.x;
    int base = tid * CHUNK;
    int s = 0;
    for (int j = 0; j < CHUNK; j++) {
        int i = base + j;
        if (i < NN) s += g_deg[i];
    }
    csum[tid] = s;
    __syncthreads();
    for (int off = 1; off < 1024; off <<= 1) {
        int t = (tid >= off) ? csum[tid - off] : 0;
        __syncthreads();
        csum[tid] += t;
        __syncthreads();
    }
    int run = csum[tid] - s;
    for (int j = 0; j < CHUNK; j++) {
        int i = base + j;
        if (i < NN) {
            g_start[i]  = run;
            g_cursor[i] = run;
            run += g_deg[i];
        }
    }
    if (tid == 1023) g_start[NN] = csum[1023];
}
__global__ void reorder_kernel(const int* __restrict__ ei) {
    int e = blockIdx.x * blockDim.x + threadIdx.x;
    if (e < NE) {
        int dst = ei[NE + e];
        int pos = atomicAdd(&g_cursor[dst], 1);
        g_ssrc[pos] = ei[e];
    }
}

// ---------------------------------------------------------------------------
// Fused gather: z[n] = (1+eps[l])*h[n] + sum_{CSR[n]} h[src]
// One warp per node; 4-edge unroll => 12 independent loads in flight.
// ---------------------------------------------------------------------------
__global__ __launch_bounds__(256) void gather_kernel(const float* __restrict__ h,
                                                     const float* __restrict__ eps, int l) {
    int wid = threadIdx.x >> 5, lane = threadIdx.x & 31;
    int n = blockIdx.x * 8 + wid;
    if (n >= NN) return;
    int beg = g_start[n], end = g_start[n + 1];
    float a0 = 0.f, a1 = 0.f, a2 = 0.f;
    float b0 = 0.f, b1 = 0.f, b2 = 0.f;
    float c0 = 0.f, c1 = 0.f, c2 = 0.f;
    float e0 = 0.f, e1 = 0.f, e2 = 0.f;
    int e = beg;
    for (; e + 4 <= end; e += 4) {
        int s0 = g_ssrc[e], s1 = g_ssrc[e + 1], s2 = g_ssrc[e + 2], s3 = g_ssrc[e + 3];
        const float* p0 = h + (size_t)s0 * DIM + lane;
        const float* p1 = h + (size_t)s1 * DIM + lane;
        const float* p2 = h + (size_t)s2 * DIM + lane;
        const float* p3 = h + (size_t)s3 * DIM + lane;
        a0 += p0[0];  a1 += p0[32];  a2 += p0[64];
        b0 += p1[0];  b1 += p1[32];  b2 += p1[64];
        c0 += p2[0];  c1 += p2[32];  c2 += p2[64];
        e0 += p3[0];  e1 += p3[32];  e2 += p3[64];
    }
    for (; e < end; e++) {
        const float* p = h + (size_t)g_ssrc[e] * DIM + lane;
        a0 += p[0]; a1 += p[32]; a2 += p[64];
    }
    float sc = 1.0f + eps[l];
    const float* hp = h + (size_t)n * DIM + lane;
    float* zp = g_z + (size_t)n * DIM + lane;
    zp[0]  = fmaf(sc, hp[0],  (a0 + b0) + (c0 + e0));
    zp[32] = fmaf(sc, hp[32], (a1 + b1) + (c1 + e1));
    zp[64] = fmaf(sc, hp[64], (a2 + b2) + (c2 + e2));
}

// ---------------------------------------------------------------------------
// Weight prep
// ---------------------------------------------------------------------------
__global__ void prep_w1(const float* __restrict__ W1) {
    int i = blockIdx.x * blockDim.x + threadIdx.x;
    if (i >= 3 * 192 * 96) return;
    int l = i / 18432, r = i % 18432;
    int n = r / 96, k = r % 96;
    float v = W1[(size_t)l * 96 * 192 + k * 192 + n];
    __nv_bfloat16 h, lo; split_bf16(v, h, lo);
    g_w1h[l * 192 * P1 + n * P1 + k] = h;
    g_w1l[l * 192 * P1 + n * P1 + k] = lo;
}
__global__ void prep_w2(const float* __restrict__ W2) {
    int i = blockIdx.x * blockDim.x + threadIdx.x;
    if (i >= 3 * 96 * 192) return;
    int l = i / 18432, r = i % 18432;
    int n = r / 192, k = r % 192;
    float v = W2[(size_t)l * 192 * 96 + k * 96 + n];
    __nv_bfloat16 h, lo; split_bf16(v, h, lo);
    g_w2h[l * 96 * P2 + n * P2 + k] = h;
    g_w2l[l * 96 * P2 + n * P2 + k] = lo;
}

// ---------------------------------------------------------------------------
// Fused layer: h = relu( relu(z@W1+b1) @ W2 + b2 )   (z1 kept in smem)
// 256 threads, 8 warps. gemm1: 128x192xK96; gemm2: 128x96xK192.
// smem (dynamic, 211200 B):
//   [0,768)        bias1
//   [768,1152)     bias2
//   [1280,...]     A hi (26624) | A lo (26624) | B1h (39936) | B1l (39936)
//   [134400,...]   B2h (38400) | B2l (38400)
// After gemm1: z1h @1280 (51200), z1l @52480 (51200)  (overlays A/B1 region)
// After gemm2: sC fp32 @1280 (51200)
// ---------------------------------------------------------------------------
#define OFF_B1S  0
#define OFF_B2S  768
#define OFF_AH   1280
#define OFF_AL   27904
#define OFF_B1H  54528
#define OFF_B1L  94464
#define OFF_B2H  134400
#define OFF_B2L  172800
#define OFF_Z1H  1280
#define OFF_Z1L  52480
#define OFF_SC   1280
#define L_SMEM   211200

__global__ __launch_bounds__(256) void layer_fused(
    const float* __restrict__ A,
    const __nv_bfloat16* __restrict__ B1h, const __nv_bfloat16* __restrict__ B1l,
    const float* __restrict__ bias1,
    const __nv_bfloat16* __restrict__ B2h, const __nv_bfloat16* __restrict__ B2l,
    const float* __restrict__ bias2, float* __restrict__ C)
{
    extern __shared__ char sm[];
    float* b1s = (float*)(sm + OFF_B1S);
    float* b2s = (float*)(sm + OFF_B2S);
    __nv_bfloat16* sAh  = (__nv_bfloat16*)(sm + OFF_AH);
    __nv_bfloat16* sAl  = (__nv_bfloat16*)(sm + OFF_AL);
    __nv_bfloat16* sB1h = (__nv_bfloat16*)(sm + OFF_B1H);
    __nv_bfloat16* sB1l = (__nv_bfloat16*)(sm + OFF_B1L);
    __nv_bfloat16* sB2h = (__nv_bfloat16*)(sm + OFF_B2H);
    __nv_bfloat16* sB2l = (__nv_bfloat16*)(sm + OFF_B2L);
    __nv_bfloat16* z1h  = (__nv_bfloat16*)(sm + OFF_Z1H);
    __nv_bfloat16* z1l  = (__nv_bfloat16*)(sm + OFF_Z1L);
    int tid = threadIdx.x, lane = tid & 31, wid = tid >> 5;
    int row0 = blockIdx.x * 128;

    // ---- stage loads ----
    if (tid < 192) b1s[tid] = bias1[tid];
    if (tid < 96)  b2s[tid] = bias2[tid];
    for (int i = tid; i < 2496; i += 256) {          // B1: 192*104*2/16
        ((uint4*)sB1h)[i] = ((const uint4*)B1h)[i];
        ((uint4*)sB1l)[i] = ((const uint4*)B1l)[i];
    }
    for (int i = tid; i < 2400; i += 256) {          // B2: 96*200*2/16
        ((uint4*)sB2h)[i] = ((const uint4*)B2h)[i];
        ((uint4*)sB2l)[i] = ((const uint4*)B2l)[i];
    }
    const float4* gA = (const float4*)(A + (size_t)row0 * DIM);
    for (int i = tid; i < 3072; i += 256) {          // A: 128*96 fp32
        int r = i / 24, c = i % 24;
        float4 v = gA[i];
        __nv_bfloat16 h0,l0,h1,l1,h2,l2,h3,l3;
        split_bf16(v.x,h0,l0); split_bf16(v.y,h1,l1);
        split_bf16(v.z,h2,l2); split_bf16(v.w,h3,l3);
        uint32_t off = r * P1 + c * 4;
        *(uint2*)&sAh[off] = make_uint2(pack2(h0,h1), pack2(h2,h3));
        *(uint2*)&sAl[off] = make_uint2(pack2(l0,l1), pack2(l2,l3));
    }
    __syncthreads();

    int wm = wid >> 1, wn = wid & 1;
    int arow = wm * 32 + (lane >> 2);
    int kc = (lane & 3) * 2;

    // ---- gemm1 mainloop: 128x192, K=96 ----
    {
        float d[2][12][4];
#pragma unroll
        for (int m = 0; m < 2; m++)
#pragma unroll
            for (int j = 0; j < 12; j++)
#pragma unroll
                for (int t = 0; t < 4; t++) d[m][j][t] = 0.0f;

#pragma unroll
        for (int k0 = 0; k0 < 96; k0 += 16) {
            uint32_t ah[2][4], al[2][4];
#pragma unroll
            for (int m = 0; m < 2; m++) {
                uint32_t o = (uint32_t)(arow + m * 16) * P1 + k0 + kc;
                ah[m][0] = *(uint32_t*)&sAh[o];
                ah[m][1] = *(uint32_t*)&sAh[o + 8 * P1];
                ah[m][2] = *(uint32_t*)&sAh[o + 8];
                ah[m][3] = *(uint32_t*)&sAh[o + 8 * P1 + 8];
                al[m][0] = *(uint32_t*)&sAl[o];
                al[m][1] = *(uint32_t*)&sAl[o + 8 * P1];
                al[m][2] = *(uint32_t*)&sAl[o + 8];
                al[m][3] = *(uint32_t*)&sAl[o + 8 * P1 + 8];
            }
#pragma unroll
            for (int j = 0; j < 12; j++) {
                uint32_t ob = (uint32_t)(wn * 96 + j * 8 + (lane >> 2)) * P1 + k0 + kc;
                uint32_t bh[2] = { *(uint32_t*)&sB1h[ob], *(uint32_t*)&sB1h[ob + 8] };
                uint32_t bl[2] = { *(uint32_t*)&sB1l[ob], *(uint32_t*)&sB1l[ob + 8] };
#pragma unroll
                for (int m = 0; m < 2; m++) {
                    mma16816(d[m][j], ah[m], bh);
                    mma16816(d[m][j], ah[m], bl);
                    mma16816(d[m][j], al[m], bh);
                }
            }
        }
        __syncthreads();   // everyone done reading sA/sB1 before overwrite

        // ---- z1 = relu(d + b1) -> smem hi/lo ----
#pragma unroll
        for (int m = 0; m < 2; m++) {
            int r1 = wm * 32 + m * 16 + (lane >> 2);
#pragma unroll
            for (int j = 0; j < 12; j++) {
                int c0 = wn * 96 + j * 8 + (lane & 3) * 2;
                float v0 = fmaxf(d[m][j][0] + b1s[c0],     0.0f);
                float v1 = fmaxf(d[m][j][1] + b1s[c0 + 1], 0.0f);
                float v2 = fmaxf(d[m][j][2] + b1s[c0],     0.0f);
                float v3 = fmaxf(d[m][j][3] + b1s[c0 + 1], 0.0f);
                __nv_bfloat16 h0,l0,h1,l1,h2,l2,h3,l3;
                split_bf16(v0,h0,l0); split_bf16(v1,h1,l1);
                split_bf16(v2,h2,l2); split_bf16(v3,h3,l3);
                *(uint32_t*)&z1h[r1 * P2 + c0]       = pack2(h0, h1);
                *(uint32_t*)&z1l[r1 * P2 + c0]       = pack2(l0, l1);
                *(uint32_t*)&z1h[(r1 + 8) * P2 + c0] = pack2(h2, h3);
                *(uint32_t*)&z1l[(r1 + 8) * P2 + c0] = pack2(l2, l3);
            }
        }
    }
    __syncthreads();

    // ---- gemm2 mainloop: 128x96, K=192 ----
    float d2[2][6][4];
#pragma unroll
    for (int m = 0; m < 2; m++)
#pragma unroll
        for (int j = 0; j < 6; j++)
#pragma unroll
            for (int t = 0; t < 4; t++) d2[m][j][t] = 0.0f;

#pragma unroll
    for (int k0 = 0; k0 < 192; k0 += 16) {
        uint32_t ah[2][4], al[2][4];
#pragma unroll
        for (int m = 0; m < 2; m++) {
            uint32_t o = (uint32_t)(arow + m * 16) * P2 + k0 + kc;
            ah[m][0] = *(uint32_t*)&z1h[o];
            ah[m][1] = *(uint32_t*)&z1h[o + 8 * P2];
            ah[m][2] = *(uint32_t*)&z1h[o + 8];
            ah[m][3] = *(uint32_t*)&z1h[o + 8 * P2 + 8];
            al[m][0] = *(uint32_t*)&z1l[o];
            al[m][1] = *(uint32_t*)&z1l[o + 8 * P2];
            al[m][2] = *(uint32_t*)&z1l[o + 8];
            al[m][3] = *(uint32_t*)&z1l[o + 8 * P2 + 8];
        }
#pragma unroll
        for (int j = 0; j < 6; j++) {
            uint32_t ob = (uint32_t)(wn * 48 + j * 8 + (lane >> 2)) * P2 + k0 + kc;
            uint32_t bh[2] = { *(uint32_t*)&sB2h[ob], *(uint32_t*)&sB2h[ob + 8] };
            uint32_t bl[2] = { *(uint32_t*)&sB2l[ob], *(uint32_t*)&sB2l[ob + 8] };
#pragma unroll
            for (int m = 0; m < 2; m++) {
                mma16816(d2[m][j], ah[m], bh);
                mma16816(d2[m][j], ah[m], bl);
                mma16816(d2[m][j], al[m], bh);
            }
        }
    }
    __syncthreads();   // z1 dead; reuse as sC

    float* sC = (float*)(sm + OFF_SC);               // [128][100]
#pragma unroll
    for (int m = 0; m < 2; m++) {
        int r1 = wm * 32 + m * 16 + (lane >> 2);
#pragma unroll
        for (int j = 0; j < 6; j++) {
            int c0 = wn * 48 + j * 8 + (lane & 3) * 2;
            *(float2*)&sC[r1 * 100 + c0] = make_float2(
                fmaxf(d2[m][j][0] + b2s[c0],     0.0f),
                fmaxf(d2[m][j][1] + b2s[c0 + 1], 0.0f));
            *(float2*)&sC[(r1 + 8) * 100 + c0] = make_float2(
                fmaxf(d2[m][j][2] + b2s[c0],     0.0f),
                fmaxf(d2[m][j][3] + b2s[c0 + 1], 0.0f));
        }
    }
    __syncthreads();
    float4* gC = (float4*)(C + (size_t)row0 * DIM);
    for (int i = tid; i < 3072; i += 256) {
        int r = i / 24, c = i % 24;
        gC[i] = *(float4*)&sC[r * 100 + c * 4];
    }
}

// ---------------------------------------------------------------------------
// Pool + final MLP
// ---------------------------------------------------------------------------
__global__ void zero_g_kernel() {
    int i = blockIdx.x * blockDim.x + threadIdx.x;
    if (i < NG * DIM) g_g[i] = 0.0f;
}
__global__ void pool_kernel(const float* __restrict__ h,
                            const int* __restrict__ batch) {
    int i = blockIdx.x * blockDim.x + threadIdx.x;
    if (i < NN * 24) {
        int n = i / 24, c = i % 24;
        int b = batch[n];
        float4 v = *(const float4*)&h[(size_t)n * DIM + c * 4];
        atomicAdd((float4*)&g_g[(size_t)b * DIM] + c, v);
    }
}
__global__ __launch_bounds__(256) void final_kernel(
    const float* __restrict__ fW1, const float* __restrict__ fb1,
    const float* __restrict__ fW2, const float* __restrict__ fb2,
    float* __restrict__ out)
{
    __shared__ float gs[NG * DIM];
    __shared__ float t1[NG * DIM];
    int tid = threadIdx.x;
    for (int i = tid; i < NG * DIM; i += 256) gs[i] = g_g[i];
    __syncthreads();
    for (int o = tid; o < NG * DIM; o += 256) {
        int gi = o / DIM, j = o % DIM;
        float acc = fb1[j];
#pragma unroll 8
        for (int k = 0; k < DIM; k++)
            acc = fmaf(gs[gi * DIM + k], fW1[k * DIM + j], acc);
        t1[o] = fmaxf(acc, 0.0f);
    }
    __syncthreads();
    if (tid < NG) {
        float acc = fb2[0];
#pragma unroll 8
        for (int k = 0; k < DIM; k++)
            acc = fmaf(t1[tid * DIM + k], fW2[k], acc);
        out[tid] = acc;
    }
}

// ---------------------------------------------------------------------------
extern "C" void kernel_launch(void* const* d_in, const int* in_sizes, int n_in,
                              void* d_out, int out_size) {
    const float* x     = (const float*)d_in[0];
    const int*   ei    = (const int*)d_in[1];
    const int*   batch = (const int*)d_in[2];
    const float* W1    = (const float*)d_in[3];
    const float* b1    = (const float*)d_in[4];
    const float* W2    = (const float*)d_in[5];
    const float* b2    = (const float*)d_in[6];
    const float* eps   = (const float*)d_in[7];
    const float* fW1   = (const float*)d_in[8];
    const float* fb1   = (const float*)d_in[9];
    const float* fW2   = (const float*)d_in[10];
    const float* fb2   = (const float*)d_in[11];
    float*       out   = (float*)d_out;

    static bool attr_done = false;
    if (!attr_done) {
        cudaFuncSetAttribute(layer_fused, cudaFuncAttributeMaxDynamicSharedMemorySize, L_SMEM);
        attr_done = true;
    }

    float *zp, *h0p, *h1p;
    __nv_bfloat16 *w1hp, *w1lp, *w2hp, *w2lp;
    cudaGetSymbolAddress((void**)&zp,   g_z);
    cudaGetSymbolAddress((void**)&h0p,  g_h0);
    cudaGetSymbolAddress((void**)&h1p,  g_h1);
    cudaGetSymbolAddress((void**)&w1hp, g_w1h);
    cudaGetSymbolAddress((void**)&w1lp, g_w1l);
    cudaGetSymbolAddress((void**)&w2hp, g_w2h);
    cudaGetSymbolAddress((void**)&w2lp, g_w2l);
    float* hbufs[2] = {h0p, h1p};

    // CSR build
    zero_deg_kernel<<<(NN + 255) / 256, 256>>>();
    hist_kernel<<<(NE + 255) / 256, 256>>>(ei);
    scan_kernel<<<1, 1024>>>();
    reorder_kernel<<<(NE + 255) / 256, 256>>>(ei);

    prep_w1<<<216, 256>>>(W1);
    prep_w2<<<216, 256>>>(W2);

    const int tiles = NNP / 128;   // 391
    const float* hin = x;
    for (int l = 0; l < 3; l++) {
        gather_kernel<<<(NN + 7) / 8, 256>>>(hin, eps, l);
        float* hout = hbufs[l & 1];
        layer_fused<<<tiles, 256, L_SMEM>>>(
            zp, w1hp + l * 192 * P1, w1lp + l * 192 * P1, b1 + (size_t)l * H2,
            w2hp + l * 96 * P2, w2lp + l * 96 * P2, b2 + (size_t)l * DIM, hout);
        hin = hout;
    }

    zero_g_kernel<<<(NG * DIM + 255) / 256, 256>>>();
    pool_kernel<<<(NN * 24 + 255) / 256, 256>>>(hin, batch);
    final_kernel<<<1, 256>>>(fW1, fb1, fW2, fb2, out);
}